// round 1
// baseline (speedup 1.0000x reference)
#include <cuda_runtime.h>
#include <cstdint>

#define NPMAX 100000
#define NCC   80
#define NGMAX 300
#define EPSF  1e-7f
#define C_V   0.4052847345693511f   // 4/pi^2

// ---- scratch (static device arrays; no runtime allocation) ----
__device__ float d_probT[(size_t)NCC * NPMAX];   // 32 MB, [class][pred]
__device__ float d_px1[NPMAX], d_py1[NPMAX], d_px2[NPMAX], d_py2[NPMAX];
__device__ float d_parea[NPMAX], d_patan[NPMAX], d_pcx[NPMAX], d_pcy[NPMAX];
__device__ float d_gx1[NGMAX], d_gy1[NGMAX], d_gx2[NGMAX], d_gy2[NGMAX];
__device__ float d_garea[NGMAX], d_gatan[NGMAX], d_gcx[NGMAX], d_gcy[NGMAX];
__device__ int   d_gcls[NGMAX];

// ---------------- per-prediction box prep ----------------
__global__ void prep_pred_kernel(const float* __restrict__ preds, int NP) {
    int p = blockIdx.x * blockDim.x + threadIdx.x;
    if (p >= NP) return;
    const float* r = preds + (size_t)p * (5 + NCC);
    float xc = r[0], yc = r[1], w = r[2], h = r[3];
    float x1 = xc - 0.5f * w, y1 = yc - 0.5f * h;
    float x2 = xc + 0.5f * w, y2 = yc + 0.5f * h;
    d_px1[p] = x1; d_py1[p] = y1; d_px2[p] = x2; d_py2[p] = y2;
    d_parea[p] = fmaxf(x2 - x1, 0.f) * fmaxf(y2 - y1, 0.f);
    float wp = fmaxf(x2 - x1, EPSF), hp = fmaxf(y2 - y1, EPSF);
    d_patan[p] = atanf(wp / hp);
    d_pcx[p] = 0.5f * (x1 + x2);
    d_pcy[p] = 0.5f * (y1 + y2);
}

// ---------------- per-gt prep ----------------
__global__ void prep_gt_kernel(const float* __restrict__ gt_boxes,
                               const int* __restrict__ gt_classes, int NG) {
    int g = blockIdx.x * blockDim.x + threadIdx.x;
    if (g >= NG) return;
    float x1 = gt_boxes[g * 4 + 0], y1 = gt_boxes[g * 4 + 1];
    float x2 = gt_boxes[g * 4 + 2], y2 = gt_boxes[g * 4 + 3];
    d_gx1[g] = x1; d_gy1[g] = y1; d_gx2[g] = x2; d_gy2[g] = y2;
    d_garea[g] = fmaxf(x2 - x1, 0.f) * fmaxf(y2 - y1, 0.f);
    float wg = fmaxf(x2 - x1, EPSF), hg = fmaxf(y2 - y1, EPSF);
    d_gatan[g] = atanf(wg / hg);
    d_gcx[g] = 0.5f * (x1 + x2);
    d_gcy[g] = 0.5f * (y1 + y2);
    d_gcls[g] = gt_classes[g];
}

// ---------------- sigmoid + transpose: probT[c][p] ----------------
// Block = 256 threads, handles 64 preds x 80 classes via padded smem tile.
__global__ void sig_transpose_kernel(const float* __restrict__ preds, int NP) {
    __shared__ float tile[64][NCC + 1];  // +1 pad -> conflict-free transposed reads
    int p0 = blockIdx.x * 64;
    int nblk = min(64, NP - p0);
    // load (coalesced along class dim), apply sigmoid
    for (int i = threadIdx.x; i < 64 * NCC; i += blockDim.x) {
        int pp = i / NCC, cc = i - pp * NCC;
        float v = 0.f;
        if (pp < nblk) v = preds[(size_t)(p0 + pp) * (5 + NCC) + 5 + cc];
        tile[pp][cc] = 1.0f / (1.0f + __expf(-v));
    }
    __syncthreads();
    // store transposed (coalesced along pred dim)
    for (int i = threadIdx.x; i < NCC * 64; i += blockDim.x) {
        int cc = i / 64, pp = i - cc * 64;
        if (pp < nblk)
            d_probT[(size_t)cc * NP + p0 + pp] = tile[pp][cc];
    }
}

// ---------------- cost matrix ----------------
__global__ void cost_kernel(float* __restrict__ cost, int NP, int NG) {
    __shared__ float sx1[NGMAX], sy1[NGMAX], sx2[NGMAX], sy2[NGMAX];
    __shared__ float sar[NGMAX], sat[NGMAX], scx[NGMAX], scy[NGMAX];
    __shared__ int   scl[NGMAX];
    for (int g = threadIdx.x; g < NG; g += blockDim.x) {
        sx1[g] = d_gx1[g]; sy1[g] = d_gy1[g]; sx2[g] = d_gx2[g]; sy2[g] = d_gy2[g];
        sar[g] = d_garea[g]; sat[g] = d_gatan[g]; scx[g] = d_gcx[g]; scy[g] = d_gcy[g];
        scl[g] = d_gcls[g];
    }
    __syncthreads();
    int p = blockIdx.x * blockDim.x + threadIdx.x;
    if (p >= NP) return;

    float px1 = d_px1[p], py1 = d_py1[p], px2 = d_px2[p], py2 = d_py2[p];
    float parea = d_parea[p], patan = d_patan[p], pcx = d_pcx[p], pcy = d_pcy[p];

    for (int g = 0; g < NG; ++g) {
        float gx1 = sx1[g], gy1 = sy1[g], gx2 = sx2[g], gy2 = sy2[g];
        float ix1 = fmaxf(px1, gx1), iy1 = fmaxf(py1, gy1);
        float ix2 = fminf(px2, gx2), iy2 = fminf(py2, gy2);
        float inter = fmaxf(ix2 - ix1, 0.f) * fmaxf(iy2 - iy1, 0.f);
        float uni = parea + sar[g] - inter + EPSF;
        float iou = __fdividef(inter, uni);
        float dx = pcx - scx[g], dy = pcy - scy[g];
        float d2 = dx * dx + dy * dy;
        float cw = fmaxf(fmaxf(px2, gx2) - fminf(px1, gx1), EPSF);
        float ch = fmaxf(fmaxf(py2, gy2) - fminf(py1, gy1), EPSF);
        float c2 = cw * cw + ch * ch + EPSF;
        float dat = sat[g] - patan;
        float v = C_V * dat * dat;
        float alpha = __fdividef(v, 1.0f - iou + v + EPSF);
        float ciou = iou - __fdividef(d2, c2) - alpha * v;
        float cls = d_probT[(size_t)scl[g] * NP + p];
        float c = 0.75f * (1.0f - cls) + 1.0f * (1.0f - fminf(fmaxf(ciou, 0.f), 1.f));
        cost[(size_t)g * NP + p] = c;
    }
}

// ---------------- per-gt exact top-K (K<=10) ----------------
// key = (float_bits(cost) << 32) | p  -> min-order == top_k(-cost) with
// ties broken by lower index, exactly matching jax.lax.top_k.
#define TKT 256
__global__ void topk_kernel(const float* __restrict__ cost, float* __restrict__ out,
                            int NP, int NG,
                            const int* __restrict__ epoch_p,
                            const int* __restrict__ tot_p) {
    int g = blockIdx.x;
    int ep = epoch_p[0];
    int te = tot_p[0];
    float t = (float)ep / (float)max(1, te - 1);
    int K = (int)rintf(10.0f - 9.0f * t);
    K = min(10, max(1, K));
    K = min(K, NP);

    unsigned long long loc[10];
#pragma unroll
    for (int i = 0; i < 10; ++i) loc[i] = ~0ULL;

    const float* row = cost + (size_t)g * NP;
    for (int p = threadIdx.x; p < NP; p += TKT) {
        unsigned long long key =
            ((unsigned long long)__float_as_uint(row[p]) << 32) | (unsigned)p;
        if (key < loc[9]) {
            int j = 9;
            while (j > 0 && loc[j - 1] > key) { loc[j] = loc[j - 1]; --j; }
            loc[j] = key;
        }
    }

    __shared__ unsigned long long lists[TKT][10];
    __shared__ unsigned long long red[TKT];
    __shared__ int head[TKT];
#pragma unroll
    for (int i = 0; i < 10; ++i) lists[threadIdx.x][i] = loc[i];
    head[threadIdx.x] = 0;
    __syncthreads();

    for (int r = 0; r < K; ++r) {
        unsigned long long cand = lists[threadIdx.x][head[threadIdx.x]];
        red[threadIdx.x] = cand;
        __syncthreads();
        for (int s = TKT / 2; s > 0; s >>= 1) {
            if (threadIdx.x < s)
                red[threadIdx.x] = min(red[threadIdx.x], red[threadIdx.x + s]);
            __syncthreads();
        }
        unsigned long long win = red[0];
        if (cand == win) head[threadIdx.x]++;   // key unique (contains p)
        if (threadIdx.x == 0) {
            int p = (int)(unsigned)(win & 0xffffffffULL);
            size_t base = (size_t)NG * NP + 2 * ((size_t)g * K + r);
            out[base + 0] = (float)p;
            out[base + 1] = (float)g;
        }
        __syncthreads();
    }
}

extern "C" void kernel_launch(void* const* d_in, const int* in_sizes, int n_in,
                              void* d_out, int out_size) {
    const float* preds      = (const float*)d_in[0];
    const float* gt_boxes   = (const float*)d_in[1];
    const int*   gt_classes = (const int*)d_in[2];
    const int*   epoch      = (const int*)d_in[3];
    const int*   tot        = (const int*)d_in[4];

    int NP = in_sizes[0] / (5 + NCC);
    int NG = in_sizes[2];
    float* out = (float*)d_out;

    prep_pred_kernel<<<(NP + 255) / 256, 256>>>(preds, NP);
    prep_gt_kernel<<<(NG + 255) / 256, 256>>>(gt_boxes, gt_classes, NG);
    sig_transpose_kernel<<<(NP + 63) / 64, 256>>>(preds, NP);
    cost_kernel<<<(NP + 255) / 256, 256>>>(out, NP, NG);
    topk_kernel<<<NG, TKT>>>(out, out, NP, NG, epoch, tot);
}

// round 2
// speedup vs baseline: 1.0084x; 1.0084x over previous
#include <cuda_runtime.h>
#include <cstdint>

#define NPMAX 100000
#define NCC   80
#define NGMAX 300
#define EPSF  1e-7f
#define C_V   0.4052847345693511f   // 4/pi^2

// ---- scratch (static device arrays; no runtime allocation) ----
__device__ float d_probT[(size_t)NCC * NPMAX];   // 32 MB, [class][pred]
__device__ float d_px1[NPMAX], d_py1[NPMAX], d_px2[NPMAX], d_py2[NPMAX];
__device__ float d_parea[NPMAX], d_patan[NPMAX], d_pcx[NPMAX], d_pcy[NPMAX];
__device__ float d_gx1[NGMAX], d_gy1[NGMAX], d_gx2[NGMAX], d_gy2[NGMAX];
__device__ float d_garea[NGMAX], d_gatan[NGMAX], d_gcx[NGMAX], d_gcy[NGMAX];
__device__ int   d_gcls[NGMAX];

// ---------------- per-prediction box prep ----------------
__global__ void prep_pred_kernel(const float* __restrict__ preds, int NP) {
    int p = blockIdx.x * blockDim.x + threadIdx.x;
    if (p >= NP) return;
    const float* r = preds + (size_t)p * (5 + NCC);
    float xc = r[0], yc = r[1], w = r[2], h = r[3];
    float x1 = xc - 0.5f * w, y1 = yc - 0.5f * h;
    float x2 = xc + 0.5f * w, y2 = yc + 0.5f * h;
    d_px1[p] = x1; d_py1[p] = y1; d_px2[p] = x2; d_py2[p] = y2;
    d_parea[p] = fmaxf(x2 - x1, 0.f) * fmaxf(y2 - y1, 0.f);
    float wp = fmaxf(x2 - x1, EPSF), hp = fmaxf(y2 - y1, EPSF);
    d_patan[p] = atanf(wp / hp);
    d_pcx[p] = 0.5f * (x1 + x2);
    d_pcy[p] = 0.5f * (y1 + y2);
}

// ---------------- per-gt prep ----------------
__global__ void prep_gt_kernel(const float* __restrict__ gt_boxes,
                               const int* __restrict__ gt_classes, int NG) {
    int g = blockIdx.x * blockDim.x + threadIdx.x;
    if (g >= NG) return;
    float x1 = gt_boxes[g * 4 + 0], y1 = gt_boxes[g * 4 + 1];
    float x2 = gt_boxes[g * 4 + 2], y2 = gt_boxes[g * 4 + 3];
    d_gx1[g] = x1; d_gy1[g] = y1; d_gx2[g] = x2; d_gy2[g] = y2;
    d_garea[g] = fmaxf(x2 - x1, 0.f) * fmaxf(y2 - y1, 0.f);
    float wg = fmaxf(x2 - x1, EPSF), hg = fmaxf(y2 - y1, EPSF);
    d_gatan[g] = atanf(wg / hg);
    d_gcx[g] = 0.5f * (x1 + x2);
    d_gcy[g] = 0.5f * (y1 + y2);
    d_gcls[g] = gt_classes[g];
}

// ---------------- sigmoid + transpose: probT[c][p] ----------------
// Block = 256 threads, handles 64 preds x 80 classes via padded smem tile.
__global__ void sig_transpose_kernel(const float* __restrict__ preds, int NP) {
    __shared__ float tile[64][NCC + 1];  // +1 pad -> conflict-free transposed reads
    int p0 = blockIdx.x * 64;
    int nblk = min(64, NP - p0);
    // load (coalesced along class dim), apply sigmoid
    for (int i = threadIdx.x; i < 64 * NCC; i += blockDim.x) {
        int pp = i / NCC, cc = i - pp * NCC;
        float v = 0.f;
        if (pp < nblk) v = preds[(size_t)(p0 + pp) * (5 + NCC) + 5 + cc];
        tile[pp][cc] = 1.0f / (1.0f + __expf(-v));
    }
    __syncthreads();
    // store transposed (coalesced along pred dim)
    for (int i = threadIdx.x; i < NCC * 64; i += blockDim.x) {
        int cc = i / 64, pp = i - cc * 64;
        if (pp < nblk)
            d_probT[(size_t)cc * NP + p0 + pp] = tile[pp][cc];
    }
}

// ---------------- cost matrix ----------------
__global__ void cost_kernel(float* __restrict__ cost, int NP, int NG) {
    __shared__ float sx1[NGMAX], sy1[NGMAX], sx2[NGMAX], sy2[NGMAX];
    __shared__ float sar[NGMAX], sat[NGMAX], scx[NGMAX], scy[NGMAX];
    __shared__ int   scl[NGMAX];
    for (int g = threadIdx.x; g < NG; g += blockDim.x) {
        sx1[g] = d_gx1[g]; sy1[g] = d_gy1[g]; sx2[g] = d_gx2[g]; sy2[g] = d_gy2[g];
        sar[g] = d_garea[g]; sat[g] = d_gatan[g]; scx[g] = d_gcx[g]; scy[g] = d_gcy[g];
        scl[g] = d_gcls[g];
    }
    __syncthreads();
    int p = blockIdx.x * blockDim.x + threadIdx.x;
    if (p >= NP) return;

    float px1 = d_px1[p], py1 = d_py1[p], px2 = d_px2[p], py2 = d_py2[p];
    float parea = d_parea[p], patan = d_patan[p], pcx = d_pcx[p], pcy = d_pcy[p];

    for (int g = 0; g < NG; ++g) {
        float gx1 = sx1[g], gy1 = sy1[g], gx2 = sx2[g], gy2 = sy2[g];
        float ix1 = fmaxf(px1, gx1), iy1 = fmaxf(py1, gy1);
        float ix2 = fminf(px2, gx2), iy2 = fminf(py2, gy2);
        float inter = fmaxf(ix2 - ix1, 0.f) * fmaxf(iy2 - iy1, 0.f);
        float uni = parea + sar[g] - inter + EPSF;
        float iou = __fdividef(inter, uni);
        float dx = pcx - scx[g], dy = pcy - scy[g];
        float d2 = dx * dx + dy * dy;
        float cw = fmaxf(fmaxf(px2, gx2) - fminf(px1, gx1), EPSF);
        float ch = fmaxf(fmaxf(py2, gy2) - fminf(py1, gy1), EPSF);
        float c2 = cw * cw + ch * ch + EPSF;
        float dat = sat[g] - patan;
        float v = C_V * dat * dat;
        float alpha = __fdividef(v, 1.0f - iou + v + EPSF);
        float ciou = iou - __fdividef(d2, c2) - alpha * v;
        float cls = d_probT[(size_t)scl[g] * NP + p];
        float c = 0.75f * (1.0f - cls) + 1.0f * (1.0f - fminf(fmaxf(ciou, 0.f), 1.f));
        cost[(size_t)g * NP + p] = c;
    }
}

// ---------------- per-gt exact top-K (K<=10) ----------------
// key = (float_bits(cost) << 32) | p  -> min-order == top_k(-cost) with
// ties broken by lower index, exactly matching jax.lax.top_k.
#define TKT 256
__global__ void topk_kernel(const float* __restrict__ cost, float* __restrict__ out,
                            int NP, int NG,
                            const int* __restrict__ epoch_p,
                            const int* __restrict__ tot_p) {
    int g = blockIdx.x;
    int ep = epoch_p[0];
    int te = tot_p[0];
    float t = (float)ep / (float)max(1, te - 1);
    int K = (int)rintf(10.0f - 9.0f * t);
    K = min(10, max(1, K));
    K = min(K, NP);

    unsigned long long loc[10];
#pragma unroll
    for (int i = 0; i < 10; ++i) loc[i] = ~0ULL;

    const float* row = cost + (size_t)g * NP;
    for (int p = threadIdx.x; p < NP; p += TKT) {
        unsigned long long key =
            ((unsigned long long)__float_as_uint(row[p]) << 32) | (unsigned)p;
        if (key < loc[9]) {
            int j = 9;
            while (j > 0 && loc[j - 1] > key) { loc[j] = loc[j - 1]; --j; }
            loc[j] = key;
        }
    }

    __shared__ unsigned long long lists[TKT][10];
    __shared__ unsigned long long red[TKT];
    __shared__ int head[TKT];
#pragma unroll
    for (int i = 0; i < 10; ++i) lists[threadIdx.x][i] = loc[i];
    head[threadIdx.x] = 0;
    __syncthreads();

    for (int r = 0; r < K; ++r) {
        unsigned long long cand = lists[threadIdx.x][head[threadIdx.x]];
        red[threadIdx.x] = cand;
        __syncthreads();
        for (int s = TKT / 2; s > 0; s >>= 1) {
            if (threadIdx.x < s)
                red[threadIdx.x] = min(red[threadIdx.x], red[threadIdx.x + s]);
            __syncthreads();
        }
        unsigned long long win = red[0];
        if (cand == win) head[threadIdx.x]++;   // key unique (contains p)
        if (threadIdx.x == 0) {
            int p = (int)(unsigned)(win & 0xffffffffULL);
            size_t base = (size_t)NG * NP + 2 * ((size_t)g * K + r);
            out[base + 0] = (float)p;
            out[base + 1] = (float)g;
        }
        __syncthreads();
    }
}

extern "C" void kernel_launch(void* const* d_in, const int* in_sizes, int n_in,
                              void* d_out, int out_size) {
    const float* preds      = (const float*)d_in[0];
    const float* gt_boxes   = (const float*)d_in[1];
    const int*   gt_classes = (const int*)d_in[2];
    const int*   epoch      = (const int*)d_in[3];
    const int*   tot        = (const int*)d_in[4];

    int NP = in_sizes[0] / (5 + NCC);
    int NG = in_sizes[2];
    float* out = (float*)d_out;

    prep_pred_kernel<<<(NP + 255) / 256, 256>>>(preds, NP);
    prep_gt_kernel<<<(NG + 255) / 256, 256>>>(gt_boxes, gt_classes, NG);
    sig_transpose_kernel<<<(NP + 63) / 64, 256>>>(preds, NP);
    cost_kernel<<<(NP + 255) / 256, 256>>>(out, NP, NG);
    topk_kernel<<<NG, TKT>>>(out, out, NP, NG, epoch, tot);
}